// round 14
// baseline (speedup 1.0000x reference)
#include <cuda_runtime.h>
#include <cuda_fp16.h>
#include <math.h>
#include <stdint.h>

#define TT 2048
#define HH 1024
#define FF 2816
#define NE 8
#define BM 128
#define BN 64       // gateup N per operand
#define DBN 128     // down N tile
#define BKH 32      // k per stage
#define NST 4       // pipeline stages
#define ASTR 40     // halves per smem row (32 + 8 pad)

// ---------------- scratch ----------------
__device__ int    g_cnt[NE];
__device__ int    g_tok[NE * TT];
__device__ float  g_wgt[NE * TT];
__device__ __half g_xh[(size_t)NE * TT * HH];
__device__ __half g_hh[(size_t)NE * TT * FF];

// ---------------- helpers ----------------
__device__ __forceinline__ uint32_t smem_u32(const void* p) {
    uint32_t a;
    asm("{ .reg .u64 t; cvta.to.shared.u64 t, %1; cvt.u32.u64 %0, t; }" : "=r"(a) : "l"(p));
    return a;
}
__device__ __forceinline__ void ldsm4(uint32_t* r, uint32_t a) {
    asm volatile("ldmatrix.sync.aligned.m8n8.x4.shared.b16 {%0,%1,%2,%3}, [%4];"
        : "=r"(r[0]), "=r"(r[1]), "=r"(r[2]), "=r"(r[3]) : "r"(a));
}
__device__ __forceinline__ void mma16816(float* d, const uint32_t* a, const uint32_t* b) {
    asm volatile("mma.sync.aligned.m16n8k16.row.col.f32.f16.f16.f32 "
        "{%0,%1,%2,%3}, {%4,%5,%6,%7}, {%8,%9}, {%0,%1,%2,%3};"
        : "+f"(d[0]), "+f"(d[1]), "+f"(d[2]), "+f"(d[3])
        : "r"(a[0]), "r"(a[1]), "r"(a[2]), "r"(a[3]), "r"(b[0]), "r"(b[1]));
}
__device__ __forceinline__ void cp16(uint32_t d, const void* s) {
    asm volatile("cp.async.ca.shared.global [%0], [%1], 16;" :: "r"(d), "l"(s));
}
#define CP_COMMIT() asm volatile("cp.async.commit_group;" ::: "memory")
#define CP_WAIT2()  asm volatile("cp.async.wait_group 2;" ::: "memory")

__device__ __forceinline__ void sts8(__half* dst, float4 a, float4 b) {
    __half2 h0 = __floats2half2_rn(a.x, a.y);
    __half2 h1 = __floats2half2_rn(a.z, a.w);
    __half2 h2 = __floats2half2_rn(b.x, b.y);
    __half2 h3 = __floats2half2_rn(b.z, b.w);
    uint4 v;
    v.x = *(uint32_t*)&h0; v.y = *(uint32_t*)&h1;
    v.z = *(uint32_t*)&h2; v.w = *(uint32_t*)&h3;
    *(uint4*)dst = v;
}

// ---------------- setup kernels ----------------
__global__ void zero_kernel() {
    if (threadIdx.x < NE) g_cnt[threadIdx.x] = 0;
}

__global__ void router_kernel(const float* __restrict__ x, const float* __restrict__ Wgate) {
    int warp = (blockIdx.x * blockDim.x + threadIdx.x) >> 5;
    int lane = threadIdx.x & 31;
    if (warp >= TT) return;
    const float* xt = x + (size_t)warp * HH;
    float acc[NE];
#pragma unroll
    for (int e = 0; e < NE; e++) acc[e] = 0.f;
    for (int k = lane; k < HH; k += 32) {
        float xv = xt[k];
#pragma unroll
        for (int e = 0; e < NE; e++) acc[e] += xv * Wgate[e * HH + k];
    }
#pragma unroll
    for (int off = 16; off > 0; off >>= 1) {
#pragma unroll
        for (int e = 0; e < NE; e++) acc[e] += __shfl_xor_sync(0xffffffffu, acc[e], off);
    }
    if (lane == 0) {
        int i0 = 0; float l0 = acc[0];
#pragma unroll
        for (int e = 1; e < NE; e++) if (acc[e] > l0) { l0 = acc[e]; i0 = e; }
        int i1 = -1; float l1 = -INFINITY;
#pragma unroll
        for (int e = 0; e < NE; e++) if (e != i0 && acc[e] > l1) { l1 = acc[e]; i1 = e; }
        float w0 = 1.f / (1.f + expf(l1 - l0));
        float w1 = 1.f - w0;
        int p0 = atomicAdd(&g_cnt[i0], 1);
        g_tok[i0 * TT + p0] = warp; g_wgt[i0 * TT + p0] = w0;
        int p1 = atomicAdd(&g_cnt[i1], 1);
        g_tok[i1 * TT + p1] = warp; g_wgt[i1 * TT + p1] = w1;
    }
}

__global__ void gather_kernel(const float* __restrict__ x) {
    int slot = blockIdx.x * 8 + (threadIdx.x >> 5);
    int lane = threadIdx.x & 31;
    int e = slot / TT, r = slot % TT;
    if (r >= g_cnt[e]) return;
    int t = g_tok[e * TT + r];
    const float4* src = (const float4*)(x + (size_t)t * HH);
    __half2* dst = (__half2*)(g_xh + (size_t)slot * HH);
#pragma unroll
    for (int q = 0; q < HH / 128; q++) {
        float4 v = src[lane + q * 32];
        dst[(lane + q * 32) * 2 + 0] = __floats2half2_rn(v.x, v.y);
        dst[(lane + q * 32) * 2 + 1] = __floats2half2_rn(v.z, v.w);
    }
}

// ---------------- gate+up: 128x64(x2 ops), 4-stage ring, B staged 2 kts ahead ----------------
__global__ __launch_bounds__(256, 2) void gateup_hmma(const float* __restrict__ Wg,
                                                      const float* __restrict__ Wu) {
    const int STG = (BM + 2 * BN) * ASTR;  // halves per stage = 10240
    extern __shared__ __half sh[];

    int e = blockIdx.z, n = g_cnt[e];
    int m0 = blockIdx.x * BM;
    if (m0 >= n) return;
    int n0 = blockIdx.y * BN;

    int tid = threadIdx.x, lane = tid & 31, wid = tid >> 5;
    int wm = wid >> 2, wn = wid & 3;
    uint32_t sb = smem_u32(sh);

    const __half* xab = g_xh + (size_t)e * TT * HH;
    const float*  wgb = Wg + (size_t)e * FF * HH;
    const float*  wub = Wu + (size_t)e * FF * HH;

    // A cp.async mapping: 128 rows x 4 chunks(16B) = 512, 2/thread
    const __half* asrc[2]; uint32_t adst[2];
#pragma unroll
    for (int i = 0; i < 2; i++) {
        int ch = tid + i * 256, r = ch >> 2, c = ch & 3;
        int rc = m0 + r; if (rc >= n) rc = n - 1;
        asrc[i] = xab + (size_t)rc * HH + c * 8;
        adst[i] = sb + (r * ASTR + c * 8) * 2;
    }
    // B: 64 rows x 4 chunks(8 floats) per op, 1 chunk/thread/op
    int brow = tid >> 2, bc = tid & 3;
    const float* gsrc = wgb + (size_t)(n0 + brow) * HH + bc * 8;
    const float* usrc = wub + (size_t)(n0 + brow) * HH + bc * 8;
    __half* bgst = sh + BM * ASTR + brow * ASTR + bc * 8;
    __half* bust = bgst + BN * ASTR;

    // fragment base addresses (stage 0)
    int seg = lane >> 3, li = lane & 7;
    uint32_t aA[4], aG, aU;
#pragma unroll
    for (int i = 0; i < 4; i++) {
        int row = wm * 64 + i * 16 + li + (seg & 1) * 8;
        aA[i] = sb + (row * ASTR + (seg >> 1) * 8) * 2;
    }
    {
        int row = wn * 16 + li + (seg >> 1) * 8;
        aG = sb + (BM * ASTR + row * ASTR + (seg & 1) * 8) * 2;
        aU = aG + BN * ASTR * 2;
    }

    float accg[4][2][4] = {}, accu[4][2][4] = {};
    const int KT = HH / BKH;  // 32

    // ---- prologue: A stages 0..2 via cp.async (3 groups); B stages 0..1 via LDG+STS ----
#pragma unroll
    for (int s = 0; s < 3; s++) {
        cp16(adst[0] + s * STG * 2, asrc[0] + s * BKH);
        cp16(adst[1] + s * STG * 2, asrc[1] + s * BKH);
        CP_COMMIT();
    }
#pragma unroll
    for (int s = 0; s < 2; s++) {
        float4 g0 = *(const float4*)(gsrc + s * BKH), g1 = *(const float4*)(gsrc + s * BKH + 4);
        float4 u0 = *(const float4*)(usrc + s * BKH), u1 = *(const float4*)(usrc + s * BKH + 4);
        sts8(bgst + s * STG, g0, g1);
        sts8(bust + s * STG, u0, u1);
    }

    for (int kt = 0; kt < KT; kt++) {
        CP_WAIT2();           // stage kt's A group arrived
        __syncthreads();      // stage kt's B STS (written at kt-2) visible; ring slot freed

        uint32_t so = (uint32_t)((kt & 3) * STG * 2);
        // issue A for stage kt+3
        if (kt + 3 < KT) {
            uint32_t po = (uint32_t)(((kt + 3) & 3) * STG * 2);
            cp16(adst[0] + po, asrc[0] + (kt + 3) * BKH);
            cp16(adst[1] + po, asrc[1] + (kt + 3) * BKH);
        }
        CP_COMMIT();          // empty group OK near end; keeps group accounting uniform
        // LDG B for stage kt+2 (consumed by STS after mma: ~full-kt latency slack)
        float4 vg0, vg1, vu0, vu1;
        bool bmore = (kt + 2 < KT);
        if (bmore) {
            int pk = (kt + 2) * BKH;
            vg0 = *(const float4*)(gsrc + pk); vg1 = *(const float4*)(gsrc + pk + 4);
            vu0 = *(const float4*)(usrc + pk); vu1 = *(const float4*)(usrc + pk + 4);
        }
#pragma unroll
        for (int ks = 0; ks < 2; ks++) {
            uint32_t af[4][4], bg[4], bu[4];
            ldsm4(bg, aG + so + ks * 32);
            ldsm4(bu, aU + so + ks * 32);
#pragma unroll
            for (int i = 0; i < 4; i++) ldsm4(af[i], aA[i] + so + ks * 32);
#pragma unroll
            for (int i = 0; i < 4; i++)
#pragma unroll
                for (int j = 0; j < 2; j++) {
                    mma16816(accg[i][j], af[i], &bg[j * 2]);
                    mma16816(accu[i][j], af[i], &bu[j * 2]);
                }
        }
        if (bmore) {
            int ss = (kt + 2) & 3;
            sts8(bgst + ss * STG, vg0, vg1);
            sts8(bust + ss * STG, vu0, vu1);
        }
    }

    // epilogue: SwiGLU -> fp16 g_hh
#pragma unroll
    for (int i = 0; i < 4; i++) {
        int row0 = m0 + wm * 64 + i * 16 + (lane >> 2);
        int row1 = row0 + 8;
#pragma unroll
        for (int j = 0; j < 2; j++) {
            int col = n0 + wn * 16 + j * 8 + (lane & 3) * 2;
            if (row0 < n) {
                float a0 = accg[i][j][0], a1 = accg[i][j][1];
                float h0 = (a0 / (1.f + __expf(-a0))) * accu[i][j][0];
                float h1 = (a1 / (1.f + __expf(-a1))) * accu[i][j][1];
                *(__half2*)(g_hh + ((size_t)e * TT + row0) * FF + col) = __floats2half2_rn(h0, h1);
            }
            if (row1 < n) {
                float a2 = accg[i][j][2], a3 = accg[i][j][3];
                float h2 = (a2 / (1.f + __expf(-a2))) * accu[i][j][2];
                float h3 = (a3 / (1.f + __expf(-a3))) * accu[i][j][3];
                *(__half2*)(g_hh + ((size_t)e * TT + row1) * FF + col) = __floats2half2_rn(h2, h3);
            }
        }
    }
}

// ---------------- down: 128x128, 4-stage ring, B staged 2 kts ahead, fused atomics ----------------
__global__ __launch_bounds__(256, 2) void down_hmma(const float* __restrict__ Wd,
                                                    float* __restrict__ out) {
    const int STG = (BM + DBN) * ASTR;  // 10240 halves
    extern __shared__ __half sh[];

    int e = blockIdx.z, n = g_cnt[e];
    int m0 = blockIdx.x * BM;
    if (m0 >= n) return;
    int n0 = blockIdx.y * DBN;

    int tid = threadIdx.x, lane = tid & 31, wid = tid >> 5;
    int wm = wid >> 2, wn = wid & 3;
    uint32_t sb = smem_u32(sh);

    const __half* hab = g_hh + (size_t)e * TT * FF;
    const float*  wdb = Wd + (size_t)e * HH * FF;

    const __half* asrc[2]; uint32_t adst[2];
#pragma unroll
    for (int i = 0; i < 2; i++) {
        int ch = tid + i * 256, r = ch >> 2, c = ch & 3;
        int rc = m0 + r; if (rc >= n) rc = n - 1;
        asrc[i] = hab + (size_t)rc * FF + c * 8;
        adst[i] = sb + (r * ASTR + c * 8) * 2;
    }
    // B: 128 rows x 4 chunks(8 floats) = 512 tasks, 2/thread
    const float* bsrc[2]; __half* bst[2];
#pragma unroll
    for (int i = 0; i < 2; i++) {
        int task = tid + i * 256, r = task >> 2, c = task & 3;
        bsrc[i] = wdb + (size_t)(n0 + r) * FF + c * 8;
        bst[i] = sh + BM * ASTR + r * ASTR + c * 8;
    }

    int seg = lane >> 3, li = lane & 7;
    uint32_t aA[4], aB[2];
#pragma unroll
    for (int i = 0; i < 4; i++) {
        int row = wm * 64 + i * 16 + li + (seg & 1) * 8;
        aA[i] = sb + (row * ASTR + (seg >> 1) * 8) * 2;
    }
#pragma unroll
    for (int jj = 0; jj < 2; jj++) {
        int row = wn * 32 + jj * 16 + li + (seg >> 1) * 8;
        aB[jj] = sb + (BM * ASTR + row * ASTR + (seg & 1) * 8) * 2;
    }

    float acc[4][4][4] = {};
    const int KT = FF / BKH;  // 88

    // prologue: A stages 0..2, B stages 0..1
#pragma unroll
    for (int s = 0; s < 3; s++) {
        cp16(adst[0] + s * STG * 2, asrc[0] + s * BKH);
        cp16(adst[1] + s * STG * 2, asrc[1] + s * BKH);
        CP_COMMIT();
    }
#pragma unroll
    for (int s = 0; s < 2; s++) {
#pragma unroll
        for (int i = 0; i < 2; i++) {
            float4 b0 = *(const float4*)(bsrc[i] + s * BKH);
            float4 b1 = *(const float4*)(bsrc[i] + s * BKH + 4);
            sts8(bst[i] + s * STG, b0, b1);
        }
    }

    for (int kt = 0; kt < KT; kt++) {
        CP_WAIT2();
        __syncthreads();

        uint32_t so = (uint32_t)((kt & 3) * STG * 2);
        if (kt + 3 < KT) {
            uint32_t po = (uint32_t)(((kt + 3) & 3) * STG * 2);
            cp16(adst[0] + po, asrc[0] + (kt + 3) * BKH);
            cp16(adst[1] + po, asrc[1] + (kt + 3) * BKH);
        }
        CP_COMMIT();
        float4 vb00, vb01, vb10, vb11;
        bool bmore = (kt + 2 < KT);
        if (bmore) {
            int pk = (kt + 2) * BKH;
            vb00 = *(const float4*)(bsrc[0] + pk); vb01 = *(const float4*)(bsrc[0] + pk + 4);
            vb10 = *(const float4*)(bsrc[1] + pk); vb11 = *(const float4*)(bsrc[1] + pk + 4);
        }
#pragma unroll
        for (int ks = 0; ks < 2; ks++) {
            uint32_t af[4][4], bf[8];
            ldsm4(&bf[0], aB[0] + so + ks * 32);
            ldsm4(&bf[4], aB[1] + so + ks * 32);
#pragma unroll
            for (int i = 0; i < 4; i++) ldsm4(af[i], aA[i] + so + ks * 32);
#pragma unroll
            for (int i = 0; i < 4; i++)
#pragma unroll
                for (int j = 0; j < 4; j++) mma16816(acc[i][j], af[i], &bf[j * 2]);
        }
        if (bmore) {
            int ss = (kt + 2) & 3;
            sts8(bst[0] + ss * STG, vb00, vb01);
            sts8(bst[1] + ss * STG, vb10, vb11);
        }
    }

    // epilogue: scale by combine weight, atomicAdd into out
#pragma unroll
    for (int i = 0; i < 4; i++) {
        int row0 = m0 + wm * 64 + i * 16 + (lane >> 2);
        int row1 = row0 + 8;
        bool v0 = row0 < n, v1 = row1 < n;
        int t0 = 0; float w0 = 0.f;
        if (v0) { t0 = g_tok[e * TT + row0]; w0 = g_wgt[e * TT + row0]; }
        int t1 = 0; float w1 = 0.f;
        if (v1) { t1 = g_tok[e * TT + row1]; w1 = g_wgt[e * TT + row1]; }
#pragma unroll
        for (int j = 0; j < 4; j++) {
            int col = n0 + wn * 32 + j * 8 + (lane & 3) * 2;
            if (v0) {
                float* p = out + (size_t)t0 * HH + col;
                atomicAdd(p + 0, acc[i][j][0] * w0);
                atomicAdd(p + 1, acc[i][j][1] * w0);
            }
            if (v1) {
                float* p = out + (size_t)t1 * HH + col;
                atomicAdd(p + 0, acc[i][j][2] * w1);
                atomicAdd(p + 1, acc[i][j][3] * w1);
            }
        }
    }
}

// ---------------- launch ----------------
extern "C" void kernel_launch(void* const* d_in, const int* in_sizes, int n_in,
                              void* d_out, int out_size) {
    const float* x     = (const float*)d_in[0];
    const float* Wgate = (const float*)d_in[1];
    const float* Wg    = (const float*)d_in[2];
    const float* Wu    = (const float*)d_in[3];
    const float* Wd    = (const float*)d_in[4];
    float* out = (float*)d_out;

    const int GU_SMEM = NST * (BM + 2 * BN) * ASTR * 2;  // 81920 B
    const int DN_SMEM = NST * (BM + DBN) * ASTR * 2;     // 81920 B
    cudaFuncSetAttribute(gateup_hmma, cudaFuncAttributeMaxDynamicSharedMemorySize, GU_SMEM);
    cudaFuncSetAttribute(down_hmma,   cudaFuncAttributeMaxDynamicSharedMemorySize, DN_SMEM);

    cudaMemsetAsync(out, 0, (size_t)TT * HH * sizeof(float));
    zero_kernel<<<1, 32>>>();
    router_kernel<<<TT / 8, 256>>>(x, Wgate);
    gather_kernel<<<NE * TT / 8, 256>>>(x);
    gateup_hmma<<<dim3(TT / 128, FF / BN, NE), 256, GU_SMEM>>>(Wg, Wu);
    down_hmma<<<dim3(TT / 128, HH / DBN, NE), 256, DN_SMEM>>>(Wd, out);
}

// round 16
// speedup vs baseline: 1.0647x; 1.0647x over previous
#include <cuda_runtime.h>
#include <cuda_fp16.h>
#include <math.h>
#include <stdint.h>

#define TT 2048
#define HH 1024
#define FF 2816
#define NE 8
#define BM 128
#define BN 64       // gateup N per operand
#define DBN 128     // down N tile
#define BKH 64      // k per pipeline stage (r13 proven)
#define ASTR 72     // halves per smem row (64 + 8 pad)

#define NMB   (TT / BM)          // 16 m-blocks per expert
#define NFT   (FF / BN)          // 44 gateup f-tiles
#define NGT   (HH / DBN)         // 8 down n-tiles
#define NGU   (NE * NFT * NMB)   // 5632 gateup-role blocks
#define NDN   (NE * NGT * NMB)   // 1024 down-role blocks

// ---------------- scratch ----------------
__device__ int    g_cnt[NE];
__device__ int    g_rdy[NE * NMB];   // per-(e,mb) gateup completion counters
__device__ int    g_tok[NE * TT];
__device__ float  g_wgt[NE * TT];
__device__ __half g_xh[(size_t)NE * TT * HH];
__device__ __half g_hh[(size_t)NE * TT * FF];

// ---------------- helpers ----------------
__device__ __forceinline__ uint32_t smem_u32(const void* p) {
    uint32_t a;
    asm("{ .reg .u64 t; cvta.to.shared.u64 t, %1; cvt.u32.u64 %0, t; }" : "=r"(a) : "l"(p));
    return a;
}
__device__ __forceinline__ void ldsm4(uint32_t* r, uint32_t a) {
    asm volatile("ldmatrix.sync.aligned.m8n8.x4.shared.b16 {%0,%1,%2,%3}, [%4];"
        : "=r"(r[0]), "=r"(r[1]), "=r"(r[2]), "=r"(r[3]) : "r"(a));
}
__device__ __forceinline__ void mma16816(float* d, const uint32_t* a, const uint32_t* b) {
    asm volatile("mma.sync.aligned.m16n8k16.row.col.f32.f16.f16.f32 "
        "{%0,%1,%2,%3}, {%4,%5,%6,%7}, {%8,%9}, {%0,%1,%2,%3};"
        : "+f"(d[0]), "+f"(d[1]), "+f"(d[2]), "+f"(d[3])
        : "r"(a[0]), "r"(a[1]), "r"(a[2]), "r"(a[3]), "r"(b[0]), "r"(b[1]));
}
__device__ __forceinline__ void cp16(uint32_t d, const void* s) {
    asm volatile("cp.async.ca.shared.global [%0], [%1], 16;" :: "r"(d), "l"(s));
}
#define CP_COMMIT() asm volatile("cp.async.commit_group;" ::: "memory")
#define CP_WAIT()   asm volatile("cp.async.wait_group 0;" ::: "memory")

__device__ __forceinline__ void sts8(__half* dst, float4 a, float4 b) {
    __half2 h0 = __floats2half2_rn(a.x, a.y);
    __half2 h1 = __floats2half2_rn(a.z, a.w);
    __half2 h2 = __floats2half2_rn(b.x, b.y);
    __half2 h3 = __floats2half2_rn(b.z, b.w);
    uint4 v;
    v.x = *(uint32_t*)&h0; v.y = *(uint32_t*)&h1;
    v.z = *(uint32_t*)&h2; v.w = *(uint32_t*)&h3;
    *(uint4*)dst = v;
}

// ---------------- setup ----------------
__global__ void zero_kernel() {
    int t = threadIdx.x;
    if (t < NE) g_cnt[t] = 0;
    if (t < NE * NMB) g_rdy[t] = 0;
}

// router + gather fused: warp computes top-2 and writes both fp16 row copies
__global__ void router_gather(const float* __restrict__ x, const float* __restrict__ Wgate) {
    int warp = (blockIdx.x * blockDim.x + threadIdx.x) >> 5;
    int lane = threadIdx.x & 31;
    if (warp >= TT) return;
    const float* xt = x + (size_t)warp * HH;
    float acc[NE];
#pragma unroll
    for (int e = 0; e < NE; e++) acc[e] = 0.f;
    for (int k = lane; k < HH; k += 32) {
        float xv = xt[k];
#pragma unroll
        for (int e = 0; e < NE; e++) acc[e] += xv * Wgate[e * HH + k];
    }
#pragma unroll
    for (int off = 16; off > 0; off >>= 1) {
#pragma unroll
        for (int e = 0; e < NE; e++) acc[e] += __shfl_xor_sync(0xffffffffu, acc[e], off);
    }
    int i0 = 0, i1 = 0, p0 = 0, p1 = 0;
    if (lane == 0) {
        float l0 = acc[0];
#pragma unroll
        for (int e = 1; e < NE; e++) if (acc[e] > l0) { l0 = acc[e]; i0 = e; }
        float l1 = -INFINITY; i1 = -1;
#pragma unroll
        for (int e = 0; e < NE; e++) if (e != i0 && acc[e] > l1) { l1 = acc[e]; i1 = e; }
        float w0 = 1.f / (1.f + expf(l1 - l0));
        float w1 = 1.f - w0;
        p0 = atomicAdd(&g_cnt[i0], 1);
        g_tok[i0 * TT + p0] = warp; g_wgt[i0 * TT + p0] = w0;
        p1 = atomicAdd(&g_cnt[i1], 1);
        g_tok[i1 * TT + p1] = warp; g_wgt[i1 * TT + p1] = w1;
    }
    i0 = __shfl_sync(0xffffffffu, i0, 0); p0 = __shfl_sync(0xffffffffu, p0, 0);
    i1 = __shfl_sync(0xffffffffu, i1, 0); p1 = __shfl_sync(0xffffffffu, p1, 0);
    const float4* src = (const float4*)xt;
    __half2* d0 = (__half2*)(g_xh + ((size_t)i0 * TT + p0) * HH);
    __half2* d1 = (__half2*)(g_xh + ((size_t)i1 * TT + p1) * HH);
#pragma unroll
    for (int q = 0; q < HH / 128; q++) {
        float4 v = src[lane + q * 32];
        __half2 a = __floats2half2_rn(v.x, v.y);
        __half2 b = __floats2half2_rn(v.z, v.w);
        int idx = (lane + q * 32) * 2;
        d0[idx] = a; d0[idx + 1] = b;
        d1[idx] = a; d1[idx + 1] = b;
    }
}

// ---------------- fused MoE: gateup roles [0,NGU), down roles [NGU, NGU+NDN) ----------------
__global__ __launch_bounds__(256, 2) void moe_fused(const float* __restrict__ Wg,
                                                    const float* __restrict__ Wu,
                                                    const float* __restrict__ Wd,
                                                    float* __restrict__ out) {
    extern __shared__ __half sh[];
    int tid = threadIdx.x, lane = tid & 31, wid = tid >> 5;
    int wm = wid >> 2, wn = wid & 3;
    uint32_t sb = smem_u32(sh);
    int seg = lane >> 3, li = lane & 7;
    int bx = blockIdx.x;

    if (bx < NGU) {
        // ================= GATEUP ROLE (r13 body) =================
        const int STG = (BM + 2 * BN) * ASTR;
        int e  = bx / (NFT * NMB);
        int rem = bx % (NFT * NMB);
        int ft = rem >> 4, mb = rem & (NMB - 1);
        int n  = g_cnt[e];
        int m0 = mb * BM, n0 = ft * BN;
        if (m0 >= n) {
            if (tid == 0) atomicAdd(&g_rdy[e * NMB + mb], 1);
            return;
        }

        const __half* xab = g_xh + (size_t)e * TT * HH;
        const float*  wgb = Wg + (size_t)e * FF * HH;
        const float*  wub = Wu + (size_t)e * FF * HH;

        const __half* asrc[4]; uint32_t adst[4];
#pragma unroll
        for (int i = 0; i < 4; i++) {
            int ch = tid + i * 256, r = ch >> 3, c = ch & 7;
            int rc = m0 + r; if (rc >= n) rc = n - 1;
            asrc[i] = xab + (size_t)rc * HH + c * 8;
            adst[i] = sb + (r * ASTR + c * 8) * 2;
        }
        int brow = tid >> 2, bc = tid & 3;
        const float* gsrc = wgb + (size_t)(n0 + brow) * HH + bc * 8;
        const float* usrc = wub + (size_t)(n0 + brow) * HH + bc * 8;
        __half* bgst = sh + BM * ASTR + brow * ASTR + bc * 8;
        __half* bust = bgst + BN * ASTR;

        uint32_t aA[4], aG, aU;
#pragma unroll
        for (int i = 0; i < 4; i++) {
            int row = wm * 64 + i * 16 + li + (seg & 1) * 8;
            aA[i] = sb + (row * ASTR + (seg >> 1) * 8) * 2;
        }
        {
            int row = wn * 16 + li + (seg >> 1) * 8;
            aG = sb + (BM * ASTR + row * ASTR + (seg & 1) * 8) * 2;
            aU = aG + BN * ASTR * 2;
        }

        float accg[4][2][4] = {}, accu[4][2][4] = {};
        float4 vg0, vg1, vu0, vu1;

#pragma unroll
        for (int i = 0; i < 4; i++) cp16(adst[i], asrc[i]);
        CP_COMMIT();
        vg0 = *(const float4*)gsrc; vg1 = *(const float4*)(gsrc + 4);
        vu0 = *(const float4*)usrc; vu1 = *(const float4*)(usrc + 4);
        sts8(bgst, vg0, vg1); sts8(bust, vu0, vu1);
        vg0 = *(const float4*)(gsrc + 32); vg1 = *(const float4*)(gsrc + 36);
        vu0 = *(const float4*)(usrc + 32); vu1 = *(const float4*)(usrc + 36);
        sts8(bgst + 32, vg0, vg1); sts8(bust + 32, vu0, vu1);
        CP_WAIT();
        __syncthreads();

        const int KT = HH / BKH;  // 16
        for (int kt = 0; kt < KT; kt++) {
            int cur = kt & 1;
            uint32_t so = (uint32_t)(cur * STG * 2);
            uint32_t po = (uint32_t)((cur ^ 1) * STG * 2);
            bool more = (kt + 1 < KT);
            int pk = (kt + 1) * BKH;
            if (more) {
#pragma unroll
                for (int i = 0; i < 4; i++) cp16(adst[i] + po, asrc[i] + pk);
                CP_COMMIT();
                vg0 = *(const float4*)(gsrc + pk); vg1 = *(const float4*)(gsrc + pk + 4);
                vu0 = *(const float4*)(usrc + pk); vu1 = *(const float4*)(usrc + pk + 4);
            }
#pragma unroll
            for (int ks = 0; ks < 2; ks++) {
                uint32_t af[4][4], bg[4], bu[4];
                ldsm4(bg, aG + so + ks * 32);
                ldsm4(bu, aU + so + ks * 32);
#pragma unroll
                for (int i = 0; i < 4; i++) ldsm4(af[i], aA[i] + so + ks * 32);
#pragma unroll
                for (int i = 0; i < 4; i++)
#pragma unroll
                    for (int j = 0; j < 2; j++) {
                        mma16816(accg[i][j], af[i], &bg[j * 2]);
                        mma16816(accu[i][j], af[i], &bu[j * 2]);
                    }
            }
            if (more) {
                __half* bo = bgst + (cur ^ 1) * STG;
                sts8(bo, vg0, vg1);
                sts8(bo + BN * ASTR, vu0, vu1);
                vg0 = *(const float4*)(gsrc + pk + 32); vg1 = *(const float4*)(gsrc + pk + 36);
                vu0 = *(const float4*)(usrc + pk + 32); vu1 = *(const float4*)(usrc + pk + 36);
            }
#pragma unroll
            for (int ks = 2; ks < 4; ks++) {
                uint32_t af[4][4], bg[4], bu[4];
                ldsm4(bg, aG + so + ks * 32);
                ldsm4(bu, aU + so + ks * 32);
#pragma unroll
                for (int i = 0; i < 4; i++) ldsm4(af[i], aA[i] + so + ks * 32);
#pragma unroll
                for (int i = 0; i < 4; i++)
#pragma unroll
                    for (int j = 0; j < 2; j++) {
                        mma16816(accg[i][j], af[i], &bg[j * 2]);
                        mma16816(accu[i][j], af[i], &bu[j * 2]);
                    }
            }
            if (more) {
                __half* bo = bgst + (cur ^ 1) * STG;
                sts8(bo + 32, vg0, vg1);
                sts8(bo + BN * ASTR + 32, vu0, vu1);
                CP_WAIT();
            }
            __syncthreads();
        }

        // epilogue: SwiGLU -> fp16 g_hh
#pragma unroll
        for (int i = 0; i < 4; i++) {
            int row0 = m0 + wm * 64 + i * 16 + (lane >> 2);
            int row1 = row0 + 8;
#pragma unroll
            for (int j = 0; j < 2; j++) {
                int col = n0 + wn * 16 + j * 8 + (lane & 3) * 2;
                if (row0 < n) {
                    float a0 = accg[i][j][0], a1 = accg[i][j][1];
                    float h0 = (a0 / (1.f + __expf(-a0))) * accu[i][j][0];
                    float h1 = (a1 / (1.f + __expf(-a1))) * accu[i][j][1];
                    *(__half2*)(g_hh + ((size_t)e * TT + row0) * FF + col) = __floats2half2_rn(h0, h1);
                }
                if (row1 < n) {
                    float a2 = accg[i][j][2], a3 = accg[i][j][3];
                    float h2 = (a2 / (1.f + __expf(-a2))) * accu[i][j][2];
                    float h3 = (a3 / (1.f + __expf(-a3))) * accu[i][j][3];
                    *(__half2*)(g_hh + ((size_t)e * TT + row1) * FF + col) = __floats2half2_rn(h2, h3);
                }
            }
        }
        // publish: all threads fence their g_hh stores, then one flag increment
        __threadfence();
        __syncthreads();
        if (tid == 0) atomicAdd(&g_rdy[e * NMB + mb], 1);

    } else {
        // ================= DOWN ROLE (r13 body + wait) =================
        const int STG = (BM + DBN) * ASTR;
        int j0 = bx - NGU;
        int e  = j0 / (NGT * NMB);
        int rem = j0 % (NGT * NMB);
        int nt = rem >> 4, mb = rem & (NMB - 1);
        int n  = g_cnt[e];
        int m0 = mb * BM, n0 = nt * DBN;
        if (m0 >= n) return;

        const __half* hab = g_hh + (size_t)e * TT * FF;
        const float*  wdb = Wd + (size_t)e * HH * FF;

        const __half* asrc[4]; uint32_t adst[4];
#pragma unroll
        for (int i = 0; i < 4; i++) {
            int ch = tid + i * 256, r = ch >> 3, c = ch & 7;
            int rc = m0 + r; if (rc >= n) rc = n - 1;
            asrc[i] = hab + (size_t)rc * FF + c * 8;
            adst[i] = sb + (r * ASTR + c * 8) * 2;
        }
        const float* bsrc[2]; __half* bst[2];
#pragma unroll
        for (int i = 0; i < 2; i++) {
            int task = tid + i * 256, r = task >> 2, c = task & 3;
            bsrc[i] = wdb + (size_t)(n0 + r) * FF + c * 8;
            bst[i] = sh + BM * ASTR + r * ASTR + c * 8;
        }

        uint32_t aA[4], aB[2];
#pragma unroll
        for (int i = 0; i < 4; i++) {
            int row = wm * 64 + i * 16 + li + (seg & 1) * 8;
            aA[i] = sb + (row * ASTR + (seg >> 1) * 8) * 2;
        }
#pragma unroll
        for (int jj = 0; jj < 2; jj++) {
            int row = wn * 32 + jj * 16 + li + (seg >> 1) * 8;
            aB[jj] = sb + (BM * ASTR + row * ASTR + (seg & 1) * 8) * 2;
        }

        float acc[4][4][4] = {};
        float4 vb[2][2];

        // prefetch B stage 0 FULLY (cols 0..63) BEFORE the wait — r13 structure.
        // (stage 1 is written by the mainloop at kt=0, consumed at kt=1 after sync)
#pragma unroll
        for (int i = 0; i < 2; i++) {
            float4 b0 = *(const float4*)(bsrc[i]);
            float4 b1 = *(const float4*)(bsrc[i] + 4);
            sts8(bst[i], b0, b1);
            b0 = *(const float4*)(bsrc[i] + 32);
            b1 = *(const float4*)(bsrc[i] + 36);
            sts8(bst[i] + 32, b0, b1);
        }

        // wait for all 44 gateup f-tiles of (e, mb)
        if (tid == 0) {
            while (atomicAdd(&g_rdy[e * NMB + mb], 0) < NFT) __nanosleep(256);
            __threadfence();
        }
        __syncthreads();

        // A prologue (stage 0, both half-k sets)
#pragma unroll
        for (int i = 0; i < 4; i++) cp16(adst[i], asrc[i]);
        CP_COMMIT();
        CP_WAIT();
        __syncthreads();

        const int KT = FF / BKH;  // 44
        for (int kt = 0; kt < KT; kt++) {
            int cur = kt & 1;
            uint32_t so = (uint32_t)(cur * STG * 2);
            uint32_t po = (uint32_t)((cur ^ 1) * STG * 2);
            bool more = (kt + 1 < KT);
            int pk = (kt + 1) * BKH;
            if (more) {
#pragma unroll
                for (int i = 0; i < 4; i++) cp16(adst[i] + po, asrc[i] + pk);
                CP_COMMIT();
#pragma unroll
                for (int i = 0; i < 2; i++) {
                    vb[i][0] = *(const float4*)(bsrc[i] + pk);
                    vb[i][1] = *(const float4*)(bsrc[i] + pk + 4);
                }
            }
#pragma unroll
            for (int ks = 0; ks < 2; ks++) {
                uint32_t af[4][4], bf[8];
                ldsm4(&bf[0], aB[0] + so + ks * 32);
                ldsm4(&bf[4], aB[1] + so + ks * 32);
#pragma unroll
                for (int i = 0; i < 4; i++) ldsm4(af[i], aA[i] + so + ks * 32);
#pragma unroll
                for (int i = 0; i < 4; i++)
#pragma unroll
                    for (int jj = 0; jj < 4; jj++) mma16816(acc[i][jj], af[i], &bf[jj * 2]);
            }
            if (more) {
                sts8(bst[0] + (cur ^ 1) * STG, vb[0][0], vb[0][1]);
                sts8(bst[1] + (cur ^ 1) * STG, vb[1][0], vb[1][1]);
#pragma unroll
                for (int i = 0; i < 2; i++) {
                    vb[i][0] = *(const float4*)(bsrc[i] + pk + 32);
                    vb[i][1] = *(const float4*)(bsrc[i] + pk + 36);
                }
            }
#pragma unroll
            for (int ks = 2; ks < 4; ks++) {
                uint32_t af[4][4], bf[8];
                ldsm4(&bf[0], aB[0] + so + ks * 32);
                ldsm4(&bf[4], aB[1] + so + ks * 32);
#pragma unroll
                for (int i = 0; i < 4; i++) ldsm4(af[i], aA[i] + so + ks * 32);
#pragma unroll
                for (int i = 0; i < 4; i++)
#pragma unroll
                    for (int jj = 0; jj < 4; jj++) mma16816(acc[i][jj], af[i], &bf[jj * 2]);
            }
            if (more) {
                sts8(bst[0] + (cur ^ 1) * STG + 32, vb[0][0], vb[0][1]);
                sts8(bst[1] + (cur ^ 1) * STG + 32, vb[1][0], vb[1][1]);
                CP_WAIT();
            }
            __syncthreads();
        }

        // epilogue: scale + atomicAdd into out
#pragma unroll
        for (int i = 0; i < 4; i++) {
            int row0 = m0 + wm * 64 + i * 16 + (lane >> 2);
            int row1 = row0 + 8;
            bool v0 = row0 < n, v1 = row1 < n;
            int t0 = 0; float w0 = 0.f;
            if (v0) { t0 = g_tok[e * TT + row0]; w0 = g_wgt[e * TT + row0]; }
            int t1 = 0; float w1 = 0.f;
            if (v1) { t1 = g_tok[e * TT + row1]; w1 = g_wgt[e * TT + row1]; }
#pragma unroll
            for (int jj = 0; jj < 4; jj++) {
                int col = n0 + wn * 32 + jj * 8 + (lane & 3) * 2;
                if (v0) {
                    float* p = out + (size_t)t0 * HH + col;
                    atomicAdd(p + 0, acc[i][jj][0] * w0);
                    atomicAdd(p + 1, acc[i][jj][1] * w0);
                }
                if (v1) {
                    float* p = out + (size_t)t1 * HH + col;
                    atomicAdd(p + 0, acc[i][jj][2] * w1);
                    atomicAdd(p + 1, acc[i][jj][3] * w1);
                }
            }
        }
    }
}

// ---------------- launch ----------------
extern "C" void kernel_launch(void* const* d_in, const int* in_sizes, int n_in,
                              void* d_out, int out_size) {
    const float* x     = (const float*)d_in[0];
    const float* Wgate = (const float*)d_in[1];
    const float* Wg    = (const float*)d_in[2];
    const float* Wu    = (const float*)d_in[3];
    const float* Wd    = (const float*)d_in[4];
    float* out = (float*)d_out;

    const int SMEM = 2 * (BM + 2 * BN) * ASTR * 2;  // 73728 B (same for both roles)
    cudaFuncSetAttribute(moe_fused, cudaFuncAttributeMaxDynamicSharedMemorySize, SMEM);

    cudaMemsetAsync(out, 0, (size_t)TT * HH * sizeof(float));
    zero_kernel<<<1, 256>>>();
    router_gather<<<TT / 8, 256>>>(x, Wgate);
    moe_fused<<<NGU + NDN, 256, SMEM>>>(Wg, Wu, Wd, out);
}